// round 4
// baseline (speedup 1.0000x reference)
#include <cuda_runtime.h>

// Problem constants
#define BATCH 8
#define CQ_DIM 1024
#define CR_DIM 512
#define HID_DIM 256
#define PIX 2304          // 48*48

// Scratch (allocation-free rule: __device__ globals)
__device__ float g_Q[BATCH * HID_DIM * PIX];                 // [b][o][p]
__device__ float g_K[BATCH * HID_DIM * PIX];                 // [b][o][p]
__device__ float g_S[(size_t)BATCH * PIX * PIX];             // [b][q][p]  (170 MB)

// GEMM tiling
#define BM 128
#define BN 128
#define BK 16
#define TM 8
#define TN 8
#define LDA 132   // padded leading dim for A tile (multiple of 4 -> 16B aligned rows)
#define LDB 132

// ---------------------------------------------------------------------------
// Stage 1: projection. Y[b][o][p] = sum_c W[o][c] * X[b][c][p] + bias[o]
// W row-major [HID x Kdim], X row-major per batch [Kdim x PIX].
// toK==0 -> write g_Q, toK==1 -> write g_K.
// ---------------------------------------------------------------------------
__global__ __launch_bounds__(256)
void proj_kernel(const float* __restrict__ W, const float* __restrict__ bias,
                 const float* __restrict__ X, int Kdim, int toK)
{
    __shared__ __align__(16) float As[BK * LDA];
    __shared__ __align__(16) float Bs[BK * LDB];

    const int b  = blockIdx.z;
    const float* Xb = X + (size_t)b * Kdim * PIX;
    float* Yb = (toK ? g_K : g_Q) + (size_t)b * HID_DIM * PIX;

    const int m0 = blockIdx.y * BM;   // output channel tile
    const int n0 = blockIdx.x * BN;   // pixel tile
    const int tid = threadIdx.x;
    const int tx = tid & 15, ty = tid >> 4;

    float acc[TM][TN] = {};
    float ra[TM], rb[TN];

    for (int k0 = 0; k0 < Kdim; k0 += BK) {
        // A tile: As[k][m] = W[(m0+m)*Kdim + k0+k]   (k-fastest in global)
        #pragma unroll
        for (int i = 0; i < 8; i++) {
            int idx = tid + i * 256;
            int m = idx >> 4, k = idx & 15;
            As[k * LDA + m] = W[(size_t)(m0 + m) * Kdim + (k0 + k)];
        }
        // B tile: Bs[k][n] = X[(k0+k)*PIX + n0+n]    (n-fastest, coalesced)
        #pragma unroll
        for (int i = 0; i < 8; i++) {
            int idx = tid + i * 256;
            int k = idx >> 7, n = idx & 127;
            Bs[k * LDB + n] = Xb[(size_t)(k0 + k) * PIX + (n0 + n)];
        }
        __syncthreads();
        #pragma unroll
        for (int k = 0; k < BK; k++) {
            #pragma unroll
            for (int i = 0; i < TM; i++) ra[i] = As[k * LDA + ty * TM + i];
            #pragma unroll
            for (int j = 0; j < TN; j++) rb[j] = Bs[k * LDB + tx * TN + j];
            #pragma unroll
            for (int i = 0; i < TM; i++)
                #pragma unroll
                for (int j = 0; j < TN; j++)
                    acc[i][j] += ra[i] * rb[j];
        }
        __syncthreads();
    }

    #pragma unroll
    for (int i = 0; i < TM; i++) {
        int m = m0 + ty * TM + i;
        float bv = bias[m];
        #pragma unroll
        for (int j = 0; j < TN; j++)
            Yb[(size_t)m * PIX + (n0 + tx * TN + j)] = acc[i][j] + bv;
    }
}

// ---------------------------------------------------------------------------
// Stage 2: logits. S[b][q][p] = sum_o Q[b][o][q] * K[b][o][p]   (TN GEMM)
// ---------------------------------------------------------------------------
__global__ __launch_bounds__(256)
void logits_kernel()
{
    __shared__ __align__(16) float As[BK * LDA];
    __shared__ __align__(16) float Bs[BK * LDB];

    const int b = blockIdx.z;
    const float* Qb = g_Q + (size_t)b * HID_DIM * PIX;
    const float* Kb = g_K + (size_t)b * HID_DIM * PIX;
    float* Sb = g_S + (size_t)b * PIX * PIX;

    const int q0 = blockIdx.y * BM;
    const int p0 = blockIdx.x * BN;
    const int tid = threadIdx.x;
    const int tx = tid & 15, ty = tid >> 4;

    float acc[TM][TN] = {};
    float ra[TM], rb[TN];

    for (int o0 = 0; o0 < HID_DIM; o0 += BK) {
        // As[k][m] = Q[(o0+k)*PIX + q0+m]   (m-fastest, coalesced)
        #pragma unroll
        for (int i = 0; i < 8; i++) {
            int idx = tid + i * 256;
            int k = idx >> 7, m = idx & 127;
            As[k * LDA + m] = Qb[(size_t)(o0 + k) * PIX + (q0 + m)];
        }
        // Bs[k][n] = K[(o0+k)*PIX + p0+n]
        #pragma unroll
        for (int i = 0; i < 8; i++) {
            int idx = tid + i * 256;
            int k = idx >> 7, n = idx & 127;
            Bs[k * LDB + n] = Kb[(size_t)(o0 + k) * PIX + (p0 + n)];
        }
        __syncthreads();
        #pragma unroll
        for (int k = 0; k < BK; k++) {
            #pragma unroll
            for (int i = 0; i < TM; i++) ra[i] = As[k * LDA + ty * TM + i];
            #pragma unroll
            for (int j = 0; j < TN; j++) rb[j] = Bs[k * LDB + tx * TN + j];
            #pragma unroll
            for (int i = 0; i < TM; i++)
                #pragma unroll
                for (int j = 0; j < TN; j++)
                    acc[i][j] += ra[i] * rb[j];
        }
        __syncthreads();
    }

    #pragma unroll
    for (int i = 0; i < TM; i++) {
        int q = q0 + ty * TM + i;
        #pragma unroll
        for (int j = 0; j < TN; j++)
            Sb[(size_t)q * PIX + (p0 + tx * TN + j)] = acc[i][j];
    }
}

// ---------------------------------------------------------------------------
// Stage 3: row softmax over p. One CTA (256 threads) per row; 2304 = 256*9.
// ---------------------------------------------------------------------------
__global__ __launch_bounds__(256)
void softmax_kernel()
{
    float* r = g_S + (size_t)blockIdx.x * PIX;
    const int tid = threadIdx.x;
    const int lane = tid & 31, wid = tid >> 5;

    __shared__ float smx[8];
    __shared__ float ssm[8];

    float v[9];
    float mx = -3.0e38f;
    #pragma unroll
    for (int i = 0; i < 9; i++) {
        v[i] = r[tid + i * 256];
        mx = fmaxf(mx, v[i]);
    }
    #pragma unroll
    for (int o = 16; o > 0; o >>= 1)
        mx = fmaxf(mx, __shfl_xor_sync(0xFFFFFFFFu, mx, o));
    if (lane == 0) smx[wid] = mx;
    __syncthreads();
    float rowmax = smx[0];
    #pragma unroll
    for (int i = 1; i < 8; i++) rowmax = fmaxf(rowmax, smx[i]);

    float s = 0.f;
    #pragma unroll
    for (int i = 0; i < 9; i++) {
        v[i] = __expf(v[i] - rowmax);
        s += v[i];
    }
    #pragma unroll
    for (int o = 16; o > 0; o >>= 1)
        s += __shfl_xor_sync(0xFFFFFFFFu, s, o);
    if (lane == 0) ssm[wid] = s;
    __syncthreads();
    float tot = 0.f;
    #pragma unroll
    for (int i = 0; i < 8; i++) tot += ssm[i];
    float inv = 1.0f / tot;

    #pragma unroll
    for (int i = 0; i < 9; i++)
        r[tid + i * 256] = v[i] * inv;
}

// ---------------------------------------------------------------------------
// Stage 4: attended. out[b][c][q] = sum_p S[b][q][p] * V[b][c][p]  (NT GEMM)
// V == reference_features, row-major [CR x PIX] per batch.
// ---------------------------------------------------------------------------
__global__ __launch_bounds__(256)
void attended_kernel(const float* __restrict__ rf, float* __restrict__ out)
{
    __shared__ __align__(16) float As[BK * LDA];
    __shared__ __align__(16) float Bs[BK * LDB];

    const int b = blockIdx.z;
    const float* Vb = rf + (size_t)b * CR_DIM * PIX;
    const float* Sb = g_S + (size_t)b * PIX * PIX;
    float* Ob = out + (size_t)b * CR_DIM * PIX;

    const int c0 = blockIdx.y * BM;   // channel tile (512 -> 4 tiles)
    const int q0 = blockIdx.x * BN;   // query tile
    const int tid = threadIdx.x;
    const int tx = tid & 15, ty = tid >> 4;

    float acc[TM][TN] = {};
    float ra[TM], rb[TN];

    for (int p0 = 0; p0 < PIX; p0 += BK) {
        // As[k][m] = V[(c0+m)*PIX + p0+k]    (k-fastest in global)
        #pragma unroll
        for (int i = 0; i < 8; i++) {
            int idx = tid + i * 256;
            int m = idx >> 4, k = idx & 15;
            As[k * LDA + m] = Vb[(size_t)(c0 + m) * PIX + (p0 + k)];
        }
        // Bs[k][n] = S[(q0+n)*PIX + p0+k]
        #pragma unroll
        for (int i = 0; i < 8; i++) {
            int idx = tid + i * 256;
            int n = idx >> 4, k = idx & 15;
            Bs[k * LDB + n] = Sb[(size_t)(q0 + n) * PIX + (p0 + k)];
        }
        __syncthreads();
        #pragma unroll
        for (int k = 0; k < BK; k++) {
            #pragma unroll
            for (int i = 0; i < TM; i++) ra[i] = As[k * LDA + ty * TM + i];
            #pragma unroll
            for (int j = 0; j < TN; j++) rb[j] = Bs[k * LDB + tx * TN + j];
            #pragma unroll
            for (int i = 0; i < TM; i++)
                #pragma unroll
                for (int j = 0; j < TN; j++)
                    acc[i][j] += ra[i] * rb[j];
        }
        __syncthreads();
    }

    #pragma unroll
    for (int i = 0; i < TM; i++) {
        int c = c0 + ty * TM + i;
        #pragma unroll
        for (int j = 0; j < TN; j++)
            Ob[(size_t)c * PIX + (q0 + tx * TN + j)] = acc[i][j];
    }
}

// ---------------------------------------------------------------------------
// kernel_launch: 5 launches on the default stream (graph-capturable, no
// allocations, no syncs). Input order per metadata:
//   0 query_features [8,1024,48,48] f32
//   1 reference_features [8,512,48,48] f32
//   2 Wq [256,1024] f32   3 bq [256] f32
//   4 Wk [256,512]  f32   5 bk [256] f32
// Output: [8,512,48,48] f32
// ---------------------------------------------------------------------------
extern "C" void kernel_launch(void* const* d_in, const int* in_sizes, int n_in,
                              void* d_out, int out_size)
{
    (void)in_sizes; (void)n_in; (void)out_size;
    const float* qf = (const float*)d_in[0];
    const float* rf = (const float*)d_in[1];
    const float* Wq = (const float*)d_in[2];
    const float* bq = (const float*)d_in[3];
    const float* Wk = (const float*)d_in[4];
    const float* bk = (const float*)d_in[5];
    float* out = (float*)d_out;

    dim3 blk(256);

    // Stage 1: projections
    proj_kernel<<<dim3(PIX / BN, HID_DIM / BM, BATCH), blk>>>(Wq, bq, qf, CQ_DIM, 0);
    proj_kernel<<<dim3(PIX / BN, HID_DIM / BM, BATCH), blk>>>(Wk, bk, rf, CR_DIM, 1);

    // Stage 2: logits S = Q^T K
    logits_kernel<<<dim3(PIX / BN, PIX / BM, BATCH), blk>>>();

    // Stage 3: softmax rows
    softmax_kernel<<<BATCH * PIX, blk>>>();

    // Stage 4: attended = softmax(S) @ V^T
    attended_kernel<<<dim3(PIX / BN, CR_DIM / BM, BATCH), blk>>>(rf, out);
}

// round 9
// speedup vs baseline: 3.9576x; 3.9576x over previous
#include <cuda_runtime.h>
#include <cuda_bf16.h>
#include <cstdint>

// ---------------------------------------------------------------------------
// Problem constants
// ---------------------------------------------------------------------------
#define BATCH   8
#define CQ_DIM  1024
#define CR_DIM  512
#define HID_DIM 256
#define PIX     2304          // 48*48

// ---------------------------------------------------------------------------
// Scratch (__device__ globals; allocation-free rule). NOTE: these symbols are
// ONLY referenced from device code — passing them as host-side kernel args
// binds the host shadow (ATS makes that readable => silent zeros). Never again.
// __align__(1024) guarantees 16B alignment for cp.async.
// ---------------------------------------------------------------------------
__device__ __align__(1024) float         g_S [(size_t)BATCH * PIX * PIX];     // logits fp32
__device__ __align__(1024) __nv_bfloat16 g_Sh[(size_t)BATCH * PIX * PIX];     // softmax hi
__device__ __align__(1024) __nv_bfloat16 g_Sl[(size_t)BATCH * PIX * PIX];     // softmax lo
__device__ __align__(1024) __nv_bfloat16 g_Qh[(size_t)BATCH * PIX * HID_DIM]; // Q [b][p][o]
__device__ __align__(1024) __nv_bfloat16 g_Ql[(size_t)BATCH * PIX * HID_DIM];
__device__ __align__(1024) __nv_bfloat16 g_Kh[(size_t)BATCH * PIX * HID_DIM]; // K [b][p][o]
__device__ __align__(1024) __nv_bfloat16 g_Kl[(size_t)BATCH * PIX * HID_DIM];
__device__ __align__(1024) __nv_bfloat16 g_Vh[(size_t)BATCH * CR_DIM * PIX];  // V [b][c][p]
__device__ __align__(1024) __nv_bfloat16 g_Vl[(size_t)BATCH * CR_DIM * PIX];

// ---------------------------------------------------------------------------
// SMEM tile geometry: 128 rows x 64 k bf16, padded to 72 elems (144B) per row.
// 144B row stride => ldmatrix 8-row phases advance 4 banks/row (conflict-free)
// and cp.async dst stays 16B aligned (144 = 9*16).
// ---------------------------------------------------------------------------
#define LDS_T     72
#define TILE_B    (128 * LDS_T * 2)       // 18432 bytes
#define BUF_B     (4 * TILE_B)            // Ah, Al, Bh, Bl = 73728 bytes
#define SMEM_GEMM (2 * BUF_B)             // double buffered = 147456
#define SMEM_PROJ (1 * BUF_B)             // single buffered

// ---------------------------------------------------------------------------
// PTX helpers
// ---------------------------------------------------------------------------
__device__ __forceinline__ uint32_t smem_u32(const void* p) {
    uint32_t a;
    asm("{ .reg .u64 t; cvta.to.shared.u64 t, %1; cvt.u32.u64 %0, t; }" : "=r"(a) : "l"(p));
    return a;
}
__device__ __forceinline__ void ldsm_x4(uint32_t* r, uint32_t a) {
    asm volatile("ldmatrix.sync.aligned.m8n8.x4.shared.b16 {%0,%1,%2,%3}, [%4];"
                 : "=r"(r[0]), "=r"(r[1]), "=r"(r[2]), "=r"(r[3]) : "r"(a));
}
__device__ __forceinline__ void ldsm_x2(uint32_t* r, uint32_t a) {
    asm volatile("ldmatrix.sync.aligned.m8n8.x2.shared.b16 {%0,%1}, [%2];"
                 : "=r"(r[0]), "=r"(r[1]) : "r"(a));
}
__device__ __forceinline__ void mma_bf16(float* d, const uint32_t* a, const uint32_t* b) {
    asm volatile(
        "mma.sync.aligned.m16n8k16.row.col.f32.bf16.bf16.f32 "
        "{%0,%1,%2,%3}, {%4,%5,%6,%7}, {%8,%9}, {%0,%1,%2,%3};"
        : "+f"(d[0]), "+f"(d[1]), "+f"(d[2]), "+f"(d[3])
        : "r"(a[0]), "r"(a[1]), "r"(a[2]), "r"(a[3]), "r"(b[0]), "r"(b[1]));
}
#define CP_ASYNC16(d, g) asm volatile("cp.async.cg.shared.global [%0], [%1], 16;" :: "r"(d), "l"(g))
#define CP_COMMIT()      asm volatile("cp.async.commit_group;" ::: "memory")
#define CP_WAIT1()       asm volatile("cp.async.wait_group 1;" ::: "memory")
#define CP_WAIT0()       asm volatile("cp.async.wait_group 0;" ::: "memory")

// bf16 hi/lo split of two floats, packed as u32 (elem, elem+1)
__device__ __forceinline__ void split2(float a, float b, uint32_t& hi, uint32_t& lo) {
    __nv_bfloat16 ah = __float2bfloat16(a), bh = __float2bfloat16(b);
    __nv_bfloat16 al = __float2bfloat16(a - __bfloat162float(ah));
    __nv_bfloat16 bl = __float2bfloat16(b - __bfloat162float(bh));
    hi = (uint32_t)__bfloat16_as_ushort(ah) | ((uint32_t)__bfloat16_as_ushort(bh) << 16);
    lo = (uint32_t)__bfloat16_as_ushort(al) | ((uint32_t)__bfloat16_as_ushort(bl) << 16);
}

// ---------------------------------------------------------------------------
// MMA core: one 64-wide k chunk, 3-term split product (AhBh+AhBl+AlBh).
// Warp grid 2(m) x 4(n); warp tile 64x32; atoms m16n8k16.
// ---------------------------------------------------------------------------
__device__ __forceinline__ void compute_chunk(uint32_t sAh, uint32_t sAl,
                                              uint32_t sBh, uint32_t sBl,
                                              int lane, int wm, int wn,
                                              float acc[4][4][4])
{
    const int arow = lane & 15, acol = (lane >> 4) * 8;
    const int brow = lane & 7,  bcol = ((lane >> 3) & 1) * 8;
    #pragma unroll
    for (int ks = 0; ks < 4; ks++) {
        const int kb = ks * 16;
        uint32_t ah[4][4], al[4][4], bh[4][2], bl[4][2];
        #pragma unroll
        for (int mi = 0; mi < 4; mi++) {
            uint32_t off = (uint32_t)((wm * 64 + mi * 16 + arow) * LDS_T + kb + acol) * 2;
            ldsm_x4(ah[mi], sAh + off);
            ldsm_x4(al[mi], sAl + off);
        }
        #pragma unroll
        for (int ni = 0; ni < 4; ni++) {
            uint32_t off = (uint32_t)((wn * 32 + ni * 8 + brow) * LDS_T + kb + bcol) * 2;
            ldsm_x2(bh[ni], sBh + off);
            ldsm_x2(bl[ni], sBl + off);
        }
        #pragma unroll
        for (int mi = 0; mi < 4; mi++)
            #pragma unroll
            for (int ni = 0; ni < 4; ni++) {
                mma_bf16(acc[mi][ni], ah[mi], bh[ni]);
                mma_bf16(acc[mi][ni], ah[mi], bl[ni]);
                mma_bf16(acc[mi][ni], al[mi], bh[ni]);
            }
    }
}

// cp.async tile loader: 128 rows x 64 bf16 from row-major [*, ld] (k contiguous)
__device__ __forceinline__ void cp_tile(uint32_t sdst, const __nv_bfloat16* __restrict__ src,
                                        int row0, int k0, int ld, int tid)
{
    #pragma unroll
    for (int i = 0; i < 4; i++) {
        int slot = tid + i * 256;          // 1024 slots = 128 rows * 8 chunks of 16B
        int r = slot >> 3, ch = slot & 7;
        const __nv_bfloat16* g = src + (size_t)(row0 + r) * ld + k0 + ch * 8;
        uint32_t d = sdst + (uint32_t)(r * LDS_T + ch * 8) * 2;
        CP_ASYNC16(d, g);
    }
}

// ---------------------------------------------------------------------------
// Stage 0: split V (reference features) into hi/lo planes
// ---------------------------------------------------------------------------
__global__ __launch_bounds__(256)
void vsplit_kernel(const float* __restrict__ rf)
{
    size_t i = (size_t)blockIdx.x * 512 + threadIdx.x * 2;
    float2 v = *(const float2*)(rf + i);
    uint32_t hi, lo;
    split2(v.x, v.y, hi, lo);
    *(uint32_t*)((__nv_bfloat16*)g_Vh + i) = hi;
    *(uint32_t*)((__nv_bfloat16*)g_Vl + i) = lo;
}

// ---------------------------------------------------------------------------
// Stage 1: projection. D[m=p][n=o] = sum_c X[c][p] * W[o][c] + bias[o].
// Writes split bf16 to (Qh,Ql) or (Kh,Kl), layout [b][p][o] — globals bound
// in DEVICE code. grid (HID/128, PIX/128, BATCH).
// ---------------------------------------------------------------------------
__global__ __launch_bounds__(256)
void proj_tc_kernel(const float* __restrict__ W, const float* __restrict__ bias,
                    const float* __restrict__ X, int Kdim, int toK)
{
    extern __shared__ char smem[];
    const uint32_t sb = smem_u32(smem);
    const int tid = threadIdx.x, lane = tid & 31, wid = tid >> 5;
    const int wm = wid >> 2, wn = wid & 3;
    const int b  = blockIdx.z;
    const int p0 = blockIdx.y * 128;
    const int o0 = blockIdx.x * 128;
    const float* Xb = X + (size_t)b * Kdim * PIX;
    __nv_bfloat16* Yh = (toK ? g_Kh : g_Qh) + (size_t)b * PIX * HID_DIM;
    __nv_bfloat16* Yl = (toK ? g_Kl : g_Ql) + (size_t)b * PIX * HID_DIM;

    const uint32_t sAh = sb, sAl = sb + TILE_B, sBh = sb + 2 * TILE_B, sBl = sb + 3 * TILE_B;

    float acc[4][4][4];
    #pragma unroll
    for (int mi = 0; mi < 4; mi++)
        #pragma unroll
        for (int ni = 0; ni < 4; ni++)
            #pragma unroll
            for (int r = 0; r < 4; r++) acc[mi][ni][r] = 0.f;

    const int NC = Kdim / 64;
    for (int c = 0; c < NC; c++) {
        // A tile: rows p, k = channel (transposed read, split inline)
        #pragma unroll
        for (int i = 0; i < 16; i++) {
            int slot = tid + i * 256;          // 4096 = 32 c-pairs * 128 p
            int pk = slot >> 7, r = slot & 127;
            float a = Xb[(size_t)(c * 64 + 2 * pk)     * PIX + p0 + r];
            float d = Xb[(size_t)(c * 64 + 2 * pk + 1) * PIX + p0 + r];
            uint32_t hi, lo; split2(a, d, hi, lo);
            uint32_t off = (uint32_t)(r * LDS_T + 2 * pk) * 2;
            *(uint32_t*)(smem + off) = hi;
            *(uint32_t*)(smem + TILE_B + off) = lo;
        }
        // B tile: rows o, k contiguous
        #pragma unroll
        for (int i = 0; i < 16; i++) {
            int slot = tid + i * 256;          // 4096 = 128 o * 32 c-pairs
            int r = slot >> 5, pk = slot & 31;
            float2 v = *(const float2*)&W[(size_t)(o0 + r) * Kdim + c * 64 + 2 * pk];
            uint32_t hi, lo; split2(v.x, v.y, hi, lo);
            uint32_t off = (uint32_t)(r * LDS_T + 2 * pk) * 2;
            *(uint32_t*)(smem + 2 * TILE_B + off) = hi;
            *(uint32_t*)(smem + 3 * TILE_B + off) = lo;
        }
        __syncthreads();
        compute_chunk(sAh, sAl, sBh, sBl, lane, wm, wn, acc);
        __syncthreads();
    }

    // epilogue: add bias, split, store bf16 pairs
    #pragma unroll
    for (int mi = 0; mi < 4; mi++) {
        #pragma unroll
        for (int ni = 0; ni < 4; ni++) {
            int m = p0 + wm * 64 + mi * 16 + (lane >> 2);
            int n = o0 + wn * 32 + ni * 8 + (lane & 3) * 2;
            float bv0 = __ldg(&bias[n]), bv1 = __ldg(&bias[n + 1]);
            uint32_t hi, lo;
            split2(acc[mi][ni][0] + bv0, acc[mi][ni][1] + bv1, hi, lo);
            *(uint32_t*)&Yh[(size_t)m * HID_DIM + n] = hi;
            *(uint32_t*)&Yl[(size_t)m * HID_DIM + n] = lo;
            split2(acc[mi][ni][2] + bv0, acc[mi][ni][3] + bv1, hi, lo);
            *(uint32_t*)&Yh[(size_t)(m + 8) * HID_DIM + n] = hi;
            *(uint32_t*)&Yl[(size_t)(m + 8) * HID_DIM + n] = lo;
        }
    }
}

// ---------------------------------------------------------------------------
// Unified GEMM for stages 2 & 4: D[m][n] = sum_k A[m][k]*B[n][k].
// stage==2: A=Q, B=K, D=g_S (logits). stage==4: A=V, B=softmax, D=Dout.
// All scratch pointers bound in DEVICE code. cp.async double-buffered.
// grid (N/128, M/128, BATCH).
// ---------------------------------------------------------------------------
__global__ __launch_bounds__(256)
void gemm_tc_kernel(int stage, float* __restrict__ Dout)
{
    const __nv_bfloat16 *Ah, *Al, *Bh, *Bl;
    float* D;
    int ldA, ldB, ldD, NC;
    size_t strA, strB, strD;
    if (stage == 2) {
        Ah = g_Qh; Al = g_Ql; Bh = g_Kh; Bl = g_Kl; D = g_S;
        ldA = HID_DIM; ldB = HID_DIM; ldD = PIX; NC = HID_DIM / 64;
        strA = (size_t)PIX * HID_DIM; strB = (size_t)PIX * HID_DIM; strD = (size_t)PIX * PIX;
    } else {
        Ah = g_Vh; Al = g_Vl; Bh = g_Sh; Bl = g_Sl; D = Dout;
        ldA = PIX; ldB = PIX; ldD = PIX; NC = PIX / 64;
        strA = (size_t)CR_DIM * PIX; strB = (size_t)PIX * PIX; strD = (size_t)CR_DIM * PIX;
    }

    extern __shared__ char smem[];
    const uint32_t sb = smem_u32(smem);
    const int tid = threadIdx.x, lane = tid & 31, wid = tid >> 5;
    const int wm = wid >> 2, wn = wid & 3;
    const int b  = blockIdx.z;
    const int m0 = blockIdx.y * 128;
    const int n0 = blockIdx.x * 128;
    const __nv_bfloat16* Ahb = Ah + (size_t)b * strA;
    const __nv_bfloat16* Alb = Al + (size_t)b * strA;
    const __nv_bfloat16* Bhb = Bh + (size_t)b * strB;
    const __nv_bfloat16* Blb = Bl + (size_t)b * strB;
    float* Db = D + (size_t)b * strD;

    float acc[4][4][4];
    #pragma unroll
    for (int mi = 0; mi < 4; mi++)
        #pragma unroll
        for (int ni = 0; ni < 4; ni++)
            #pragma unroll
            for (int r = 0; r < 4; r++) acc[mi][ni][r] = 0.f;

    // prefetch chunk 0 into buffer 0
    {
        uint32_t base = sb;
        cp_tile(base,              Ahb, m0, 0, ldA, tid);
        cp_tile(base + TILE_B,     Alb, m0, 0, ldA, tid);
        cp_tile(base + 2 * TILE_B, Bhb, n0, 0, ldB, tid);
        cp_tile(base + 3 * TILE_B, Blb, n0, 0, ldB, tid);
        CP_COMMIT();
    }

    for (int c = 0; c < NC; c++) {
        if (c + 1 < NC) {
            uint32_t base = sb + ((c + 1) & 1) * BUF_B;
            int k0 = (c + 1) * 64;
            cp_tile(base,              Ahb, m0, k0, ldA, tid);
            cp_tile(base + TILE_B,     Alb, m0, k0, ldA, tid);
            cp_tile(base + 2 * TILE_B, Bhb, n0, k0, ldB, tid);
            cp_tile(base + 3 * TILE_B, Blb, n0, k0, ldB, tid);
            CP_COMMIT();
            CP_WAIT1();
        } else {
            CP_WAIT0();
        }
        __syncthreads();
        uint32_t base = sb + (c & 1) * BUF_B;
        compute_chunk(base, base + TILE_B, base + 2 * TILE_B, base + 3 * TILE_B,
                      lane, wm, wn, acc);
        __syncthreads();
    }

    // epilogue: fp32 row-major, float2 stores
    #pragma unroll
    for (int mi = 0; mi < 4; mi++) {
        #pragma unroll
        for (int ni = 0; ni < 4; ni++) {
            int m = m0 + wm * 64 + mi * 16 + (lane >> 2);
            int n = n0 + wn * 32 + ni * 8 + (lane & 3) * 2;
            *(float2*)&Db[(size_t)m * ldD + n] =
                make_float2(acc[mi][ni][0], acc[mi][ni][1]);
            *(float2*)&Db[(size_t)(m + 8) * ldD + n] =
                make_float2(acc[mi][ni][2], acc[mi][ni][3]);
        }
    }
}

// ---------------------------------------------------------------------------
// Stage 3: row softmax over p; write split hi/lo weights.
// ---------------------------------------------------------------------------
__global__ __launch_bounds__(256)
void softmax_kernel()
{
    const size_t row = blockIdx.x;
    const float* r = g_S + row * PIX;
    __nv_bfloat16* wh = g_Sh + row * PIX;
    __nv_bfloat16* wl = g_Sl + row * PIX;
    const int tid = threadIdx.x;
    const int lane = tid & 31, wid = tid >> 5;

    __shared__ float smx[8];
    __shared__ float ssm[8];

    float v[9];
    float mx = -3.0e38f;
    #pragma unroll
    for (int i = 0; i < 9; i++) {
        v[i] = r[tid + i * 256];
        mx = fmaxf(mx, v[i]);
    }
    #pragma unroll
    for (int o = 16; o > 0; o >>= 1)
        mx = fmaxf(mx, __shfl_xor_sync(0xFFFFFFFFu, mx, o));
    if (lane == 0) smx[wid] = mx;
    __syncthreads();
    float rowmax = smx[0];
    #pragma unroll
    for (int i = 1; i < 8; i++) rowmax = fmaxf(rowmax, smx[i]);

    float s = 0.f;
    #pragma unroll
    for (int i = 0; i < 9; i++) {
        v[i] = __expf(v[i] - rowmax);
        s += v[i];
    }
    #pragma unroll
    for (int o = 16; o > 0; o >>= 1)
        s += __shfl_xor_sync(0xFFFFFFFFu, s, o);
    if (lane == 0) ssm[wid] = s;
    __syncthreads();
    float tot = 0.f;
    #pragma unroll
    for (int i = 0; i < 8; i++) tot += ssm[i];
    float inv = 1.0f / tot;

    #pragma unroll
    for (int i = 0; i < 9; i++) {
        float x = v[i] * inv;
        __nv_bfloat16 h = __float2bfloat16(x);
        __nv_bfloat16 l = __float2bfloat16(x - __bfloat162float(h));
        wh[tid + i * 256] = h;
        wl[tid + i * 256] = l;
    }
}

// ---------------------------------------------------------------------------
// kernel_launch
// Inputs: 0 qf [8,1024,48,48] f32, 1 rf [8,512,48,48] f32,
//         2 Wq [256,1024], 3 bq [256], 4 Wk [256,512], 5 bk [256]
// Output: [8,512,48,48] f32
// ---------------------------------------------------------------------------
extern "C" void kernel_launch(void* const* d_in, const int* in_sizes, int n_in,
                              void* d_out, int out_size)
{
    (void)in_sizes; (void)n_in; (void)out_size;
    const float* qf = (const float*)d_in[0];
    const float* rf = (const float*)d_in[1];
    const float* Wq = (const float*)d_in[2];
    const float* bq = (const float*)d_in[3];
    const float* Wk = (const float*)d_in[4];
    const float* bk = (const float*)d_in[5];
    float* out = (float*)d_out;

    // Idempotent, deterministic, capture-safe (non-stream API). Every call.
    cudaFuncSetAttribute(proj_tc_kernel,
                         cudaFuncAttributeMaxDynamicSharedMemorySize, SMEM_PROJ);
    cudaFuncSetAttribute(gemm_tc_kernel,
                         cudaFuncAttributeMaxDynamicSharedMemorySize, SMEM_GEMM);

    dim3 blk(256);

    // Stage 0: split V into hi/lo planes
    vsplit_kernel<<<(BATCH * CR_DIM * PIX) / 512, blk>>>(rf);

    // Stage 1: projections -> split Q/K [b][p][o]
    proj_tc_kernel<<<dim3(HID_DIM / 128, PIX / 128, BATCH), blk, SMEM_PROJ>>>(Wq, bq, qf, CQ_DIM, 0);
    proj_tc_kernel<<<dim3(HID_DIM / 128, PIX / 128, BATCH), blk, SMEM_PROJ>>>(Wk, bk, rf, CR_DIM, 1);

    // Stage 2: logits S[q][p] = Q.K  (M=N=PIX, K=HID)
    gemm_tc_kernel<<<dim3(PIX / 128, PIX / 128, BATCH), blk, SMEM_GEMM>>>(2, nullptr);

    // Stage 3: softmax -> split weights
    softmax_kernel<<<BATCH * PIX, blk>>>();

    // Stage 4: attended out[c][q] = V.A^T  (M=CR, N=PIX, K=PIX)
    gemm_tc_kernel<<<dim3(PIX / 128, CR_DIM / 128, BATCH), blk, SMEM_GEMM>>>(4, out);
}

// round 10
// speedup vs baseline: 4.5905x; 1.1599x over previous
#include <cuda_runtime.h>
#include <cuda_bf16.h>
#include <cstdint>

// ---------------------------------------------------------------------------
// Problem constants
// ---------------------------------------------------------------------------
#define BATCH   8
#define CQ_DIM  1024
#define CR_DIM  512
#define HID_DIM 256
#define PIX     2304          // 48*48

// ---------------------------------------------------------------------------
// Scratch (__device__ globals; allocation-free rule). These symbols are ONLY
// referenced from device code (host-side use binds the ATS-readable host
// shadow => silent zeros). __align__(1024) guarantees cp.async alignment.
// ---------------------------------------------------------------------------
__device__ __align__(1024) float         g_S [(size_t)BATCH * PIX * PIX];     // logits fp32
__device__ __align__(1024) __nv_bfloat16 g_Sh[(size_t)BATCH * PIX * PIX];     // softmax hi
__device__ __align__(1024) __nv_bfloat16 g_Sl[(size_t)BATCH * PIX * PIX];     // softmax lo
__device__ __align__(1024) __nv_bfloat16 g_Qh[(size_t)BATCH * PIX * HID_DIM]; // Q [b][p][o]
__device__ __align__(1024) __nv_bfloat16 g_Ql[(size_t)BATCH * PIX * HID_DIM];
__device__ __align__(1024) __nv_bfloat16 g_Kh[(size_t)BATCH * PIX * HID_DIM]; // K [b][p][o]
__device__ __align__(1024) __nv_bfloat16 g_Kl[(size_t)BATCH * PIX * HID_DIM];
__device__ __align__(1024) __nv_bfloat16 g_Vh[(size_t)BATCH * CR_DIM * PIX];  // V [b][c][p]
__device__ __align__(1024) __nv_bfloat16 g_Vl[(size_t)BATCH * CR_DIM * PIX];

// ---------------------------------------------------------------------------
// GEMM smem geometry (k-chunk 32): 128 rows x 32 k bf16, stride 40 elems
// (80B). 8-row ldmatrix phases advance 20 banks/row -> {0,20,8,28,16,4,24,12}
// all distinct; conflict-free. 80B keeps cp.async dst 16B-aligned.
// 4 planes x 10240B x 2 buffers = 81920B/CTA -> 2 CTAs/SM.
// ---------------------------------------------------------------------------
#define GT        40
#define GTILE_B   (128 * GT * 2)          // 10240
#define GBUF_B    (4 * GTILE_B)           // 40960
#define SMEM_GEMM (2 * GBUF_B)            // 81920

// Projection smem geometry (k-chunk 64): stride 72 elems (144B), also
// conflict-free (+4 banks/row). Single buffer: 73728B/CTA -> 2 CTAs/SM.
#define PT        72
#define PTILE_B   (128 * PT * 2)          // 18432
#define SMEM_PROJ (4 * PTILE_B)           // 73728

// ---------------------------------------------------------------------------
// PTX helpers
// ---------------------------------------------------------------------------
__device__ __forceinline__ uint32_t smem_u32(const void* p) {
    uint32_t a;
    asm("{ .reg .u64 t; cvta.to.shared.u64 t, %1; cvt.u32.u64 %0, t; }" : "=r"(a) : "l"(p));
    return a;
}
__device__ __forceinline__ void ldsm_x4(uint32_t* r, uint32_t a) {
    asm volatile("ldmatrix.sync.aligned.m8n8.x4.shared.b16 {%0,%1,%2,%3}, [%4];"
                 : "=r"(r[0]), "=r"(r[1]), "=r"(r[2]), "=r"(r[3]) : "r"(a));
}
__device__ __forceinline__ void ldsm_x2(uint32_t* r, uint32_t a) {
    asm volatile("ldmatrix.sync.aligned.m8n8.x2.shared.b16 {%0,%1}, [%2];"
                 : "=r"(r[0]), "=r"(r[1]) : "r"(a));
}
__device__ __forceinline__ void mma_bf16(float* d, const uint32_t* a, const uint32_t* b) {
    asm volatile(
        "mma.sync.aligned.m16n8k16.row.col.f32.bf16.bf16.f32 "
        "{%0,%1,%2,%3}, {%4,%5,%6,%7}, {%8,%9}, {%0,%1,%2,%3};"
        : "+f"(d[0]), "+f"(d[1]), "+f"(d[2]), "+f"(d[3])
        : "r"(a[0]), "r"(a[1]), "r"(a[2]), "r"(a[3]), "r"(b[0]), "r"(b[1]));
}
#define CP_ASYNC16(d, g) asm volatile("cp.async.cg.shared.global [%0], [%1], 16;" :: "r"(d), "l"(g))
#define CP_COMMIT()      asm volatile("cp.async.commit_group;" ::: "memory")
#define CP_WAIT1()       asm volatile("cp.async.wait_group 1;" ::: "memory")
#define CP_WAIT0()       asm volatile("cp.async.wait_group 0;" ::: "memory")

// bf16 hi/lo split of two floats, packed as u32 (elem, elem+1)
__device__ __forceinline__ void split2(float a, float b, uint32_t& hi, uint32_t& lo) {
    __nv_bfloat16 ah = __float2bfloat16(a), bh = __float2bfloat16(b);
    __nv_bfloat16 al = __float2bfloat16(a - __bfloat162float(ah));
    __nv_bfloat16 bl = __float2bfloat16(b - __bfloat162float(bh));
    hi = (uint32_t)__bfloat16_as_ushort(ah) | ((uint32_t)__bfloat16_as_ushort(bh) << 16);
    lo = (uint32_t)__bfloat16_as_ushort(al) | ((uint32_t)__bfloat16_as_ushort(bl) << 16);
}

// ---------------------------------------------------------------------------
// MMA core: T = smem row stride (elems), KS = number of k16 steps.
// 3-term split (AhBh + AhBl + AlBh). Warp grid 2(m) x 4(n); warp tile 64x32.
// ---------------------------------------------------------------------------
template<int T, int KS>
__device__ __forceinline__ void compute_chunk(uint32_t sAh, uint32_t sAl,
                                              uint32_t sBh, uint32_t sBl,
                                              int lane, int wm, int wn,
                                              float acc[4][4][4])
{
    const int arow = lane & 15, acol = (lane >> 4) * 8;
    const int brow = lane & 7,  bcol = ((lane >> 3) & 1) * 8;
    #pragma unroll
    for (int ks = 0; ks < KS; ks++) {
        const int kb = ks * 16;
        uint32_t ah[4][4], al[4][4], bh[4][2], bl[4][2];
        #pragma unroll
        for (int mi = 0; mi < 4; mi++) {
            uint32_t off = (uint32_t)((wm * 64 + mi * 16 + arow) * T + kb + acol) * 2;
            ldsm_x4(ah[mi], sAh + off);
            ldsm_x4(al[mi], sAl + off);
        }
        #pragma unroll
        for (int ni = 0; ni < 4; ni++) {
            uint32_t off = (uint32_t)((wn * 32 + ni * 8 + brow) * T + kb + bcol) * 2;
            ldsm_x2(bh[ni], sBh + off);
            ldsm_x2(bl[ni], sBl + off);
        }
        #pragma unroll
        for (int mi = 0; mi < 4; mi++)
            #pragma unroll
            for (int ni = 0; ni < 4; ni++) {
                mma_bf16(acc[mi][ni], ah[mi], bh[ni]);
                mma_bf16(acc[mi][ni], ah[mi], bl[ni]);
                mma_bf16(acc[mi][ni], al[mi], bh[ni]);
            }
    }
}

// cp.async tile loader: 128 rows x 32 bf16 (4 chunks of 16B per row)
__device__ __forceinline__ void cp_tile32(uint32_t sdst, const __nv_bfloat16* __restrict__ src,
                                          int row0, int k0, int ld, int tid)
{
    #pragma unroll
    for (int i = 0; i < 2; i++) {
        int slot = tid + i * 256;          // 512 slots = 128 rows * 4 chunks
        int r = slot >> 2, ch = slot & 3;
        const __nv_bfloat16* g = src + (size_t)(row0 + r) * ld + k0 + ch * 8;
        uint32_t d = sdst + (uint32_t)(r * GT + ch * 8) * 2;
        CP_ASYNC16(d, g);
    }
}

// ---------------------------------------------------------------------------
// Stage 0: split V (reference features) into hi/lo planes
// ---------------------------------------------------------------------------
__global__ __launch_bounds__(256)
void vsplit_kernel(const float* __restrict__ rf)
{
    size_t i = (size_t)blockIdx.x * 512 + threadIdx.x * 2;
    float2 v = *(const float2*)(rf + i);
    uint32_t hi, lo;
    split2(v.x, v.y, hi, lo);
    *(uint32_t*)((__nv_bfloat16*)g_Vh + i) = hi;
    *(uint32_t*)((__nv_bfloat16*)g_Vl + i) = lo;
}

// ---------------------------------------------------------------------------
// Stage 1: projection. D[m=p][n=o] = sum_c X[c][p] * W[o][c] + bias[o].
// Writes split bf16 to (Qh,Ql)/(Kh,Kl), layout [b][p][o].
// grid (HID/128, PIX/128, BATCH). k-chunk 64, single-buffer; 2 CTAs/SM.
// ---------------------------------------------------------------------------
__global__ __launch_bounds__(256, 2)
void proj_tc_kernel(const float* __restrict__ W, const float* __restrict__ bias,
                    const float* __restrict__ X, int Kdim, int toK)
{
    extern __shared__ char smem[];
    const uint32_t sb = smem_u32(smem);
    const int tid = threadIdx.x, lane = tid & 31, wid = tid >> 5;
    const int wm = wid >> 2, wn = wid & 3;
    const int b  = blockIdx.z;
    const int p0 = blockIdx.y * 128;
    const int o0 = blockIdx.x * 128;
    const float* Xb = X + (size_t)b * Kdim * PIX;
    __nv_bfloat16* Yh = (toK ? g_Kh : g_Qh) + (size_t)b * PIX * HID_DIM;
    __nv_bfloat16* Yl = (toK ? g_Kl : g_Ql) + (size_t)b * PIX * HID_DIM;

    float acc[4][4][4];
    #pragma unroll
    for (int mi = 0; mi < 4; mi++)
        #pragma unroll
        for (int ni = 0; ni < 4; ni++)
            #pragma unroll
            for (int r = 0; r < 4; r++) acc[mi][ni][r] = 0.f;

    const int NC = Kdim / 64;
    for (int c = 0; c < NC; c++) {
        // A tile: rows p, k = channel (transposed read, split inline)
        #pragma unroll
        for (int i = 0; i < 16; i++) {
            int slot = tid + i * 256;          // 4096 = 32 c-pairs * 128 p
            int pk = slot >> 7, r = slot & 127;
            float a = Xb[(size_t)(c * 64 + 2 * pk)     * PIX + p0 + r];
            float d = Xb[(size_t)(c * 64 + 2 * pk + 1) * PIX + p0 + r];
            uint32_t hi, lo; split2(a, d, hi, lo);
            uint32_t off = (uint32_t)(r * PT + 2 * pk) * 2;
            *(uint32_t*)(smem + off) = hi;
            *(uint32_t*)(smem + PTILE_B + off) = lo;
        }
        // B tile: rows o, k contiguous
        #pragma unroll
        for (int i = 0; i < 16; i++) {
            int slot = tid + i * 256;          // 4096 = 128 o * 32 c-pairs
            int r = slot >> 5, pk = slot & 31;
            float2 v = *(const float2*)&W[(size_t)(o0 + r) * Kdim + c * 64 + 2 * pk];
            uint32_t hi, lo; split2(v.x, v.y, hi, lo);
            uint32_t off = (uint32_t)(r * PT + 2 * pk) * 2;
            *(uint32_t*)(smem + 2 * PTILE_B + off) = hi;
            *(uint32_t*)(smem + 3 * PTILE_B + off) = lo;
        }
        __syncthreads();
        compute_chunk<PT, 4>(sb, sb + PTILE_B, sb + 2 * PTILE_B, sb + 3 * PTILE_B,
                             lane, wm, wn, acc);
        __syncthreads();
    }

    // epilogue: add bias, split, store bf16 pairs
    #pragma unroll
    for (int mi = 0; mi < 4; mi++) {
        #pragma unroll
        for (int ni = 0; ni < 4; ni++) {
            int m = p0 + wm * 64 + mi * 16 + (lane >> 2);
            int n = o0 + wn * 32 + ni * 8 + (lane & 3) * 2;
            float bv0 = __ldg(&bias[n]), bv1 = __ldg(&bias[n + 1]);
            uint32_t hi, lo;
            split2(acc[mi][ni][0] + bv0, acc[mi][ni][1] + bv1, hi, lo);
            *(uint32_t*)&Yh[(size_t)m * HID_DIM + n] = hi;
            *(uint32_t*)&Yl[(size_t)m * HID_DIM + n] = lo;
            split2(acc[mi][ni][2] + bv0, acc[mi][ni][3] + bv1, hi, lo);
            *(uint32_t*)&Yh[(size_t)(m + 8) * HID_DIM + n] = hi;
            *(uint32_t*)&Yl[(size_t)(m + 8) * HID_DIM + n] = lo;
        }
    }
}

// ---------------------------------------------------------------------------
// Unified GEMM for stages 2 & 4: D[m][n] = sum_k A[m][k]*B[n][k].
// stage==2: A=Q, B=K, D=g_S. stage==4: A=V, B=softmax, D=Dout.
// k-chunk 32, cp.async double-buffered; 2 CTAs/SM (regs capped at 128).
// grid (N/128, M/128, BATCH).
// ---------------------------------------------------------------------------
__global__ __launch_bounds__(256, 2)
void gemm_tc_kernel(int stage, float* __restrict__ Dout)
{
    const __nv_bfloat16 *Ah, *Al, *Bh, *Bl;
    float* D;
    int ldA, ldB, ldD, NC;
    size_t strA, strB, strD;
    if (stage == 2) {
        Ah = g_Qh; Al = g_Ql; Bh = g_Kh; Bl = g_Kl; D = g_S;
        ldA = HID_DIM; ldB = HID_DIM; ldD = PIX; NC = HID_DIM / 32;
        strA = (size_t)PIX * HID_DIM; strB = (size_t)PIX * HID_DIM; strD = (size_t)PIX * PIX;
    } else {
        Ah = g_Vh; Al = g_Vl; Bh = g_Sh; Bl = g_Sl; D = Dout;
        ldA = PIX; ldB = PIX; ldD = PIX; NC = PIX / 32;
        strA = (size_t)CR_DIM * PIX; strB = (size_t)PIX * PIX; strD = (size_t)CR_DIM * PIX;
    }

    extern __shared__ char smem[];
    const uint32_t sb = smem_u32(smem);
    const int tid = threadIdx.x, lane = tid & 31, wid = tid >> 5;
    const int wm = wid >> 2, wn = wid & 3;
    const int b  = blockIdx.z;
    const int m0 = blockIdx.y * 128;
    const int n0 = blockIdx.x * 128;
    const __nv_bfloat16* Ahb = Ah + (size_t)b * strA;
    const __nv_bfloat16* Alb = Al + (size_t)b * strA;
    const __nv_bfloat16* Bhb = Bh + (size_t)b * strB;
    const __nv_bfloat16* Blb = Bl + (size_t)b * strB;
    float* Db = D + (size_t)b * strD;

    float acc[4][4][4];
    #pragma unroll
    for (int mi = 0; mi < 4; mi++)
        #pragma unroll
        for (int ni = 0; ni < 4; ni++)
            #pragma unroll
            for (int r = 0; r < 4; r++) acc[mi][ni][r] = 0.f;

    // prefetch chunk 0 into buffer 0
    {
        cp_tile32(sb,              Ahb, m0, 0, ldA, tid);
        cp_tile32(sb + GTILE_B,     Alb, m0, 0, ldA, tid);
        cp_tile32(sb + 2 * GTILE_B, Bhb, n0, 0, ldB, tid);
        cp_tile32(sb + 3 * GTILE_B, Blb, n0, 0, ldB, tid);
        CP_COMMIT();
    }

    for (int c = 0; c < NC; c++) {
        if (c + 1 < NC) {
            uint32_t base = sb + ((c + 1) & 1) * GBUF_B;
            int k0 = (c + 1) * 32;
            cp_tile32(base,              Ahb, m0, k0, ldA, tid);
            cp_tile32(base + GTILE_B,     Alb, m0, k0, ldA, tid);
            cp_tile32(base + 2 * GTILE_B, Bhb, n0, k0, ldB, tid);
            cp_tile32(base + 3 * GTILE_B, Blb, n0, k0, ldB, tid);
            CP_COMMIT();
            CP_WAIT1();
        } else {
            CP_WAIT0();
        }
        __syncthreads();
        uint32_t base = sb + (c & 1) * GBUF_B;
        compute_chunk<GT, 2>(base, base + GTILE_B, base + 2 * GTILE_B, base + 3 * GTILE_B,
                             lane, wm, wn, acc);
        __syncthreads();
    }

    // epilogue: fp32 row-major, float2 stores
    #pragma unroll
    for (int mi = 0; mi < 4; mi++) {
        #pragma unroll
        for (int ni = 0; ni < 4; ni++) {
            int m = m0 + wm * 64 + mi * 16 + (lane >> 2);
            int n = n0 + wn * 32 + ni * 8 + (lane & 3) * 2;
            *(float2*)&Db[(size_t)m * ldD + n] =
                make_float2(acc[mi][ni][0], acc[mi][ni][1]);
            *(float2*)&Db[(size_t)(m + 8) * ldD + n] =
                make_float2(acc[mi][ni][2], acc[mi][ni][3]);
        }
    }
}

// ---------------------------------------------------------------------------
// Stage 3: row softmax over p; write split hi/lo weights.
// ---------------------------------------------------------------------------
__global__ __launch_bounds__(256)
void softmax_kernel()
{
    const size_t row = blockIdx.x;
    const float* r = g_S + row * PIX;
    __nv_bfloat16* wh = g_Sh + row * PIX;
    __nv_bfloat16* wl = g_Sl + row * PIX;
    const int tid = threadIdx.x;
    const int lane = tid & 31, wid = tid >> 5;

    __shared__ float smx[8];
    __shared__ float ssm[8];

    float v[9];
    float mx = -3.0e38f;
    #pragma unroll
    for (int i = 0; i < 9; i++) {
        v[i] = r[tid + i * 256];
        mx = fmaxf(mx, v[i]);
    }
    #pragma unroll
    for (int o = 16; o > 0; o >>= 1)
        mx = fmaxf(mx, __shfl_xor_sync(0xFFFFFFFFu, mx, o));
    if (lane == 0) smx[wid] = mx;
    __syncthreads();
    float rowmax = smx[0];
    #pragma unroll
    for (int i = 1; i < 8; i++) rowmax = fmaxf(rowmax, smx[i]);

    float s = 0.f;
    #pragma unroll
    for (int i = 0; i < 9; i++) {
        v[i] = __expf(v[i] - rowmax);
        s += v[i];
    }
    #pragma unroll
    for (int o = 16; o > 0; o >>= 1)
        s += __shfl_xor_sync(0xFFFFFFFFu, s, o);
    if (lane == 0) ssm[wid] = s;
    __syncthreads();
    float tot = 0.f;
    #pragma unroll
    for (int i = 0; i < 8; i++) tot += ssm[i];
    float inv = 1.0f / tot;

    #pragma unroll
    for (int i = 0; i < 9; i++) {
        float x = v[i] * inv;
        __nv_bfloat16 h = __float2bfloat16(x);
        __nv_bfloat16 l = __float2bfloat16(x - __bfloat162float(h));
        wh[tid + i * 256] = h;
        wl[tid + i * 256] = l;
    }
}

// ---------------------------------------------------------------------------
// kernel_launch
// Inputs: 0 qf [8,1024,48,48] f32, 1 rf [8,512,48,48] f32,
//         2 Wq [256,1024], 3 bq [256], 4 Wk [256,512], 5 bk [256]
// Output: [8,512,48,48] f32
// ---------------------------------------------------------------------------
extern "C" void kernel_launch(void* const* d_in, const int* in_sizes, int n_in,
                              void* d_out, int out_size)
{
    (void)in_sizes; (void)n_in; (void)out_size;
    const float* qf = (const float*)d_in[0];
    const float* rf = (const float*)d_in[1];
    const float* Wq = (const float*)d_in[2];
    const float* bq = (const float*)d_in[3];
    const float* Wk = (const float*)d_in[4];
    const float* bk = (const float*)d_in[5];
    float* out = (float*)d_out;

    // Idempotent, deterministic, capture-safe (non-stream API). Every call.
    cudaFuncSetAttribute(proj_tc_kernel,
                         cudaFuncAttributeMaxDynamicSharedMemorySize, SMEM_PROJ);
    cudaFuncSetAttribute(gemm_tc_kernel,
                         cudaFuncAttributeMaxDynamicSharedMemorySize, SMEM_GEMM);

    dim3 blk(256);

    // Stage 0: split V into hi/lo planes
    vsplit_kernel<<<(BATCH * CR_DIM * PIX) / 512, blk>>>(rf);

    // Stage 1: projections -> split Q/K [b][p][o]
    proj_tc_kernel<<<dim3(HID_DIM / 128, PIX / 128, BATCH), blk, SMEM_PROJ>>>(Wq, bq, qf, CQ_DIM, 0);
    proj_tc_kernel<<<dim3(HID_DIM / 128, PIX / 128, BATCH), blk, SMEM_PROJ>>>(Wk, bk, rf, CR_DIM, 1);

    // Stage 2: logits S[q][p] = Q.K  (M=N=PIX, K=HID)
    gemm_tc_kernel<<<dim3(PIX / 128, PIX / 128, BATCH), blk, SMEM_GEMM>>>(2, nullptr);

    // Stage 3: softmax -> split weights
    softmax_kernel<<<BATCH * PIX, blk>>>();

    // Stage 4: attended out[c][q] = V.A^T  (M=CR, N=PIX, K=PIX)
    gemm_tc_kernel<<<dim3(PIX / 128, CR_DIM / 128, BATCH), blk, SMEM_GEMM>>>(4, out);
}